// round 15
// baseline (speedup 1.0000x reference)
#include <cuda_runtime.h>
#include <cstddef>

#define NPTS 1024
#define DIM  128
#define FULLMASK 0xffffffffu
#define CAP 256

// ---- per-point scratch + sync counters (zero-init; reset at end of launch) ----
__device__ float2 g_stat[NPTS];   // (x2_j, F_j = exp(-right_j))
__device__ int    g_done;         // blocks that published their point stats
__device__ int    g_fin;          // blocks finished (for counter reset)

__device__ __forceinline__ float warp_sum(float v) {
#pragma unroll
    for (int o = 16; o > 0; o >>= 1) v += __shfl_xor_sync(FULLMASK, v, o);
    return v;
}

// atanh(min(s,1-1e-7)) via fast log; s >= 0
__device__ __forceinline__ float fast_atanh(float s) {
    s = fminf(s, 1.0f - 1e-7f);
    return 0.5f * __logf(__fdividef(1.0f + s, 1.0f - s));
}

// ---------------------------------------------------------------------------
// Single launch, one wave, 128 thr per row i.
//  step0 : stage s_xi; warp 0 reduces (x2,d1,d2), publishes g_stat[i]+s_red,
//          arrives g_done (no block-wide sync on the publish path)
//  step1 : float4 ballot compaction; ballots RECOMPUTED in pass 2 (no masks[]
//          held across the sync -> 8 fewer registers -> 9 blocks/SM)
//  dots  : quad-per-pair dot x_i.x_j -> s_d[]  (PRE-spin, hides barrier wait;
//          two d-partials for a shorter FMA chain)
//  spin  : wait g_done == gridDim (single wave -> no deadlock)
//  scal  : pair-per-lane scalar chain -> s_wb[], wa
//  step3 : dim-per-lane aggregation, unroll-2 dual accumulators (rows L1-hot)
//  step4 : expmap epilogue on warp 0
//  tail  : last block resets counters (graph-replay safe)
// ---------------------------------------------------------------------------
__global__ void __launch_bounds__(128, 9) k_fused(
    const float* __restrict__ x, const float* __restrict__ adj,
    const float* __restrict__ attw, const float* __restrict__ attb,
    float* __restrict__ out)
{
    __shared__ __align__(16) float s_xi[DIM];
    __shared__ int   s_idx[CAP];
    __shared__ float s_val[CAP];
    __shared__ float s_d[CAP];
    __shared__ float s_wb[CAP];
    __shared__ __align__(16) float s_u[4][DIM];
    __shared__ float s_red[8];
    __shared__ int   s_wcnt[4];

    const int i    = blockIdx.x;
    const int t    = threadIdx.x;          // 0..127
    const int warp = t >> 5, lane = t & 31;

    // ---- step 0: stage x_i (all); warp 0 reduces + publishes ----
    s_xi[t] = x[i * DIM + t];
    if (warp == 0) {
        float4 v  = *(const float4*)&x[i * DIM + 4 * lane];   // L1 hit
        float4 w1 = *(const float4*)&attw[4 * lane];
        float4 w2 = *(const float4*)&attw[DIM + 4 * lane];
        float x2p = v.x * v.x + v.y * v.y + v.z * v.z + v.w * v.w;
        float d1p = v.x * w1.x + v.y * w1.y + v.z * w1.z + v.w * w1.w;
        float d2p = v.x * w2.x + v.y * w2.y + v.z * w2.z + v.w * w2.w;
#pragma unroll
        for (int o = 16; o > 0; o >>= 1) {
            x2p += __shfl_xor_sync(FULLMASK, x2p, o);
            d1p += __shfl_xor_sync(FULLMASK, d1p, o);
            d2p += __shfl_xor_sync(FULLMASK, d2p, o);
        }
        if (lane == 0) {
            float pn  = sqrtf(fmaxf(x2p, 1e-15f));
            float fac = fast_atanh(pn) / pn;
            float Ei  = __expf(-(fac * d1p + attb[0]));
            g_stat[i] = make_float2(x2p, __expf(-(fac * d2p)));
            __threadfence();
            atomicAdd(&g_done, 1);                // publish ASAP
            s_red[0] = x2p; s_red[1] = Ei;
        }
    }

    // ---- step 1: float4 compaction; ballots recomputed in pass 2 ----
    const float4* arow4 = (const float4*)(adj + (size_t)i * NPTS + warp * 256);
    float4 va[2];
    va[0] = arow4[lane];
    va[1] = arow4[32 + lane];
    int mycnt = 0;
#pragma unroll
    for (int c = 0; c < 2; c++) {
        const float* vp = (const float*)&va[c];
#pragma unroll
        for (int q = 0; q < 4; q++)
            mycnt += __popc(__ballot_sync(FULLMASK, vp[q] != 0.0f));
    }
    if (lane == 0) s_wcnt[warp] = mycnt;
    __syncthreads();
    int run = 0;
#pragma unroll
    for (int w = 0; w < 4; w++) if (w < warp) run += s_wcnt[w];
#pragma unroll
    for (int c = 0; c < 2; c++) {
        const float* vp = (const float*)&va[c];
#pragma unroll
        for (int q = 0; q < 4; q++) {
            unsigned m = __ballot_sync(FULLMASK, vp[q] != 0.0f);
            if (m & (1u << lane)) {
                int pos = run + __popc(m & ((1u << lane) - 1));
                if (pos < CAP) {
                    s_idx[pos] = warp * 256 + c * 128 + lane * 4 + q;
                    s_val[pos] = vp[q];
                }
            }
            run += __popc(m);
        }
    }
    const int cnt = min(s_wcnt[0] + s_wcnt[1] + s_wcnt[2] + s_wcnt[3], CAP);
    __syncthreads();                                // s_idx/s_val visible

    // ---- dots PRE-spin: quad-per-pair, two partial chains ----
    const int slice = lane & 3;
    for (int kb = 0; kb < cnt; kb += 32) {
        int  k   = kb + warp * 8 + (lane >> 2);
        bool act = k < cnt;
        int  j   = act ? s_idx[k] : i;
        const float4* xj4 = (const float4*)(x + j * DIM);
        float d0 = 0.f, d1 = 0.f;
#pragma unroll
        for (int m = 0; m < 4; m++) {
            float4 b0  = xj4[(2 * m) * 4 + slice];
            float4 a0  = ((const float4*)s_xi)[(2 * m) * 4 + slice];
            float4 b1  = xj4[(2 * m + 1) * 4 + slice];
            float4 a1  = ((const float4*)s_xi)[(2 * m + 1) * 4 + slice];
            d0 += a0.x * b0.x + a0.y * b0.y + a0.z * b0.z + a0.w * b0.w;
            d1 += a1.x * b1.x + a1.y * b1.y + a1.z * b1.z + a1.w * b1.w;
        }
        float d = d0 + d1;
        d += __shfl_xor_sync(FULLMASK, d, 1);
        d += __shfl_xor_sync(FULLMASK, d, 2);
        if (act && slice == 0) s_d[k] = d;
    }

    // ---- spin: wait for every block's point stats (single wave) ----
    if (t == 0) {
        while (*(volatile int*)&g_done < (int)gridDim.x) __nanosleep(32);
        __threadfence();
    }
    __syncthreads();

    const float x2i  = s_red[0];
    const float Ei   = s_red[1];
    const float omi  = 1.0f - x2i;
    const float omci = fmaxf(omi, 1e-15f);

    // ---- scalar chain: pair-per-lane, one parallel round ----
    float wa_lane = 0.0f;
    for (int k = t; k < cnt; k += 128) {
        int   j  = s_idx[k];
        float av = s_val[k];
        float d  = s_d[k];
        float2 st = g_stat[j];
        float x2j = st.x;
        // attention: adj * sigmoid(left+right+b) = av / (1 + Ei*Fj)
        float sig = __fdividef(av, 1.0f + Ei * st.y);
        // pairwise logmap scalar chain
        float P   = 1.0f - 2.0f * d;
        float A   = P + x2j;                             // coeff of -x_i
        float den = fmaxf(P + x2i * x2j, 1e-15f);        // mobius denom
        float Q   = x2i * A * A - 2.0f * A * omi * d + x2j * omi * omi;
        Q = fmaxf(Q, 1e-15f * den * den);                // sn2 clamp * den^2
        float rq  = rsqrtf(Q);
        float sq  = Q * rq;                              // sqrt(Q)
        float dm  = fmaxf(den - sq, 1e-7f * den);        // atanh clip
        float ath = 0.5f * __logf(__fdividef(den + sq, dm));
        float wgt = sig * omci * ath * rq;
        wa_lane += wgt * A;
        s_wb[k] = wgt * omi;
    }
    wa_lane = warp_sum(wa_lane);
    if (lane == 0) s_red[4 + warp] = wa_lane;
    __syncthreads();

    // ---- step 3: aggregation, unroll-2 dual accumulators (rows L1-hot) ----
    float4 uA = {0.f, 0.f, 0.f, 0.f};
    float4 uB = {0.f, 0.f, 0.f, 0.f};
    int k = warp;
    for (; k + 4 < cnt; k += 8) {
        float wbA = s_wb[k];
        float4 bA = *(const float4*)(x + s_idx[k] * DIM + 4 * lane);
        float wbB = s_wb[k + 4];
        float4 bB = *(const float4*)(x + s_idx[k + 4] * DIM + 4 * lane);
        uA.x += wbA * bA.x; uA.y += wbA * bA.y; uA.z += wbA * bA.z; uA.w += wbA * bA.w;
        uB.x += wbB * bB.x; uB.y += wbB * bB.y; uB.z += wbB * bB.z; uB.w += wbB * bB.w;
    }
    if (k < cnt) {
        float wbA = s_wb[k];
        float4 bA = *(const float4*)(x + s_idx[k] * DIM + 4 * lane);
        uA.x += wbA * bA.x; uA.y += wbA * bA.y; uA.z += wbA * bA.z; uA.w += wbA * bA.w;
    }
    uA.x += uB.x; uA.y += uB.y; uA.z += uB.z; uA.w += uB.w;
    ((float4*)s_u[warp])[lane] = uA;
    __syncthreads();

    // ---- step 4: expmap epilogue (warp 0, float4 per lane covers D=128) ----
    if (warp == 0) {
        float4 u0 = ((const float4*)s_u[0])[lane];
        float4 u1 = ((const float4*)s_u[1])[lane];
        float4 u2 = ((const float4*)s_u[2])[lane];
        float4 u3 = ((const float4*)s_u[3])[lane];
        float  wa = s_red[4] + s_red[5] + s_red[6] + s_red[7];
        float4 xi = ((const float4*)s_xi)[lane];
        float4 uu;
        uu.x = (u0.x + u1.x) + (u2.x + u3.x) - wa * xi.x;
        uu.y = (u0.y + u1.y) + (u2.y + u3.y) - wa * xi.y;
        uu.z = (u0.z + u1.z) + (u2.z + u3.z) - wa * xi.z;
        uu.w = (u0.w + u1.w) + (u2.w + u3.w) - wa * xi.w;
        float su2 = uu.x * uu.x + uu.y * uu.y + uu.z * uu.z + uu.w * uu.w;
        float sxu = xi.x * uu.x + xi.y * uu.y + xi.z * uu.z + xi.w * uu.w;
#pragma unroll
        for (int o = 16; o > 0; o >>= 1) {
            su2 += __shfl_xor_sync(FULLMASK, su2, o);
            sxu += __shfl_xor_sync(FULLMASK, sxu, o);
        }
        float un   = sqrtf(fmaxf(su2, 1e-15f));
        float coef = tanhf(un / omci) / un;     // tanh(lam*un/2)/un
        float xy   = coef * sxu;
        float y2   = coef * coef * su2;
        float den  = fmaxf(1.0f + 2.0f * xy + x2i * y2, 1e-15f);
        float An   = 1.0f + 2.0f * xy + y2;
        float Bn   = omi * coef;
        float inv  = 1.0f / den;
        float4 o;
        o.x = (An * xi.x + Bn * uu.x) * inv;
        o.y = (An * xi.y + Bn * uu.y) * inv;
        o.z = (An * xi.z + Bn * uu.z) * inv;
        o.w = (An * xi.w + Bn * uu.w) * inv;
        *(float4*)&out[i * DIM + 4 * lane] = o;
    }

    // ---- tail: last block to finish resets the counters (replay-safe) ----
    if (t == 0) {
        __threadfence();
        int f = atomicAdd(&g_fin, 1);
        if (f == (int)gridDim.x - 1) { g_done = 0; g_fin = 0; }
    }
}

// ---------------------------------------------------------------------------
extern "C" void kernel_launch(void* const* d_in, const int* in_sizes, int n_in,
                              void* d_out, int out_size) {
    const float* x    = (const float*)d_in[0];   // [1,1024,128]
    const float* adj  = (const float*)d_in[1];   // [1,1024,1024]
    const float* attw = (const float*)d_in[2];   // [256]
    const float* attb = (const float*)d_in[3];   // scalar
    float* out = (float*)d_out;                  // [1,1024,128]

    k_fused<<<NPTS, 128>>>(x, adj, attw, attb, out);
}

// round 16
// speedup vs baseline: 1.1517x; 1.1517x over previous
#include <cuda_runtime.h>
#include <cstddef>

#define NPTS 1024
#define DIM  128
#define FULLMASK 0xffffffffu
#define CAP 256

// ---- per-point stat-with-flag + finish counter (zero-init; reset at tail) ----
// packed (x2 in low 32 bits, F=exp(-right) in high 32). F>0 strictly -> the
// high word doubles as the "published" flag. Single 64-bit store = atomic
// visibility (readers see all-or-nothing), so no fence is needed.
__device__ unsigned long long g_stat[NPTS];
__device__ int g_fin;             // blocks finished (for flag reset)

__device__ __forceinline__ float warp_sum(float v) {
#pragma unroll
    for (int o = 16; o > 0; o >>= 1) v += __shfl_xor_sync(FULLMASK, v, o);
    return v;
}

// atanh(min(s,1-1e-7)) via fast log; s >= 0
__device__ __forceinline__ float fast_atanh(float s) {
    s = fminf(s, 1.0f - 1e-7f);
    return 0.5f * __logf(__fdividef(1.0f + s, 1.0f - s));
}

// ---------------------------------------------------------------------------
// Single launch, NO grid barrier. Block (128 threads) per row i.
//  step0 : stage s_xi; warp 0 reduces (x2,d1,d2); lane 0 publishes
//          g_stat[i] via one 64-bit store (value == ready flag)
//  step1 : float4 ballot compaction (ballots recomputed in pass 2)
//  dots  : quad-per-pair dot x_i.x_j -> s_d[]
//  scal  : pair-per-lane scalar chain; POLLS g_stat[j] until F-bits nonzero
//          (first-try hit in steady state) -> s_wb[], wa
//  step3 : dim-per-lane aggregation, unroll-2 dual accumulators
//  step4 : expmap epilogue on warp 0
//  tail  : last block zeroes g_stat + g_fin (graph-replay safe)
// ---------------------------------------------------------------------------
__global__ void __launch_bounds__(128, 8) k_fused(
    const float* __restrict__ x, const float* __restrict__ adj,
    const float* __restrict__ attw, const float* __restrict__ attb,
    float* __restrict__ out)
{
    __shared__ __align__(16) float s_xi[DIM];
    __shared__ int   s_idx[CAP];
    __shared__ float s_val[CAP];
    __shared__ float s_d[CAP];
    __shared__ float s_wb[CAP];
    __shared__ __align__(16) float s_u[4][DIM];
    __shared__ float s_red[8];
    __shared__ int   s_wcnt[4];

    const int i    = blockIdx.x;
    const int t    = threadIdx.x;          // 0..127
    const int warp = t >> 5, lane = t & 31;

    // ---- step 0: stage x_i (all); warp 0 reduces + publishes ----
    s_xi[t] = x[i * DIM + t];
    if (warp == 0) {
        float4 v  = *(const float4*)&x[i * DIM + 4 * lane];   // L1 hit
        float4 w1 = *(const float4*)&attw[4 * lane];
        float4 w2 = *(const float4*)&attw[DIM + 4 * lane];
        float x2p = v.x * v.x + v.y * v.y + v.z * v.z + v.w * v.w;
        float d1p = v.x * w1.x + v.y * w1.y + v.z * w1.z + v.w * w1.w;
        float d2p = v.x * w2.x + v.y * w2.y + v.z * w2.z + v.w * w2.w;
#pragma unroll
        for (int o = 16; o > 0; o >>= 1) {
            x2p += __shfl_xor_sync(FULLMASK, x2p, o);
            d1p += __shfl_xor_sync(FULLMASK, d1p, o);
            d2p += __shfl_xor_sync(FULLMASK, d2p, o);
        }
        if (lane == 0) {
            float pn  = sqrtf(fmaxf(x2p, 1e-15f));
            float fac = fast_atanh(pn) / pn;
            float Ei  = __expf(-(fac * d1p + attb[0]));
            float Fi  = fmaxf(__expf(-(fac * d2p)), 1e-37f);  // strictly > 0
            union { unsigned long long u; float2 f; } p;
            p.f = make_float2(x2p, Fi);
            *(volatile unsigned long long*)&g_stat[i] = p.u;  // publish = flag
            s_red[0] = x2p; s_red[1] = Ei;
        }
    }

    // ---- step 1: float4 compaction; ballots recomputed in pass 2 ----
    const float4* arow4 = (const float4*)(adj + (size_t)i * NPTS + warp * 256);
    float4 va[2];
    va[0] = arow4[lane];
    va[1] = arow4[32 + lane];
    int mycnt = 0;
#pragma unroll
    for (int c = 0; c < 2; c++) {
        const float* vp = (const float*)&va[c];
#pragma unroll
        for (int q = 0; q < 4; q++)
            mycnt += __popc(__ballot_sync(FULLMASK, vp[q] != 0.0f));
    }
    if (lane == 0) s_wcnt[warp] = mycnt;
    __syncthreads();
    int run = 0;
#pragma unroll
    for (int w = 0; w < 4; w++) if (w < warp) run += s_wcnt[w];
#pragma unroll
    for (int c = 0; c < 2; c++) {
        const float* vp = (const float*)&va[c];
#pragma unroll
        for (int q = 0; q < 4; q++) {
            unsigned m = __ballot_sync(FULLMASK, vp[q] != 0.0f);
            if (m & (1u << lane)) {
                int pos = run + __popc(m & ((1u << lane) - 1));
                if (pos < CAP) {
                    s_idx[pos] = warp * 256 + c * 128 + lane * 4 + q;
                    s_val[pos] = vp[q];
                }
            }
            run += __popc(m);
        }
    }
    const int cnt = min(s_wcnt[0] + s_wcnt[1] + s_wcnt[2] + s_wcnt[3], CAP);
    __syncthreads();                                // s_idx/s_val/s_red visible

    // ---- dots: quad-per-pair, two partial chains ----
    const int slice = lane & 3;
    for (int kb = 0; kb < cnt; kb += 32) {
        int  k   = kb + warp * 8 + (lane >> 2);
        bool act = k < cnt;
        int  j   = act ? s_idx[k] : i;
        const float4* xj4 = (const float4*)(x + j * DIM);
        float d0 = 0.f, d1 = 0.f;
#pragma unroll
        for (int m = 0; m < 4; m++) {
            float4 b0  = xj4[(2 * m) * 4 + slice];
            float4 a0  = ((const float4*)s_xi)[(2 * m) * 4 + slice];
            float4 b1  = xj4[(2 * m + 1) * 4 + slice];
            float4 a1  = ((const float4*)s_xi)[(2 * m + 1) * 4 + slice];
            d0 += a0.x * b0.x + a0.y * b0.y + a0.z * b0.z + a0.w * b0.w;
            d1 += a1.x * b1.x + a1.y * b1.y + a1.z * b1.z + a1.w * b1.w;
        }
        float d = d0 + d1;
        d += __shfl_xor_sync(FULLMASK, d, 1);
        d += __shfl_xor_sync(FULLMASK, d, 2);
        if (act && slice == 0) s_d[k] = d;
    }
    __syncthreads();                                // s_d visible

    const float x2i  = s_red[0];
    const float Ei   = s_red[1];
    const float omi  = 1.0f - x2i;
    const float omci = fmaxf(omi, 1e-15f);

    // ---- scalar chain: pair-per-lane; per-neighbor flag poll ----
    float wa_lane = 0.0f;
    for (int k = t; k < cnt; k += 128) {
        int   j  = s_idx[k];
        float av = s_val[k];
        float d  = s_d[k];
        union { unsigned long long u; float2 f; } st;
        st.u = *(volatile unsigned long long*)&g_stat[j];
        while ((st.u >> 32) == 0ull) {              // F bits == 0 -> not yet
            __nanosleep(32);
            st.u = *(volatile unsigned long long*)&g_stat[j];
        }
        float x2j = st.f.x;
        // attention: adj * sigmoid(left+right+b) = av / (1 + Ei*Fj)
        float sig = __fdividef(av, 1.0f + Ei * st.f.y);
        // pairwise logmap scalar chain
        float P   = 1.0f - 2.0f * d;
        float A   = P + x2j;                             // coeff of -x_i
        float den = fmaxf(P + x2i * x2j, 1e-15f);        // mobius denom
        float Q   = x2i * A * A - 2.0f * A * omi * d + x2j * omi * omi;
        Q = fmaxf(Q, 1e-15f * den * den);                // sn2 clamp * den^2
        float rq  = rsqrtf(Q);
        float sq  = Q * rq;                              // sqrt(Q)
        float dm  = fmaxf(den - sq, 1e-7f * den);        // atanh clip
        float ath = 0.5f * __logf(__fdividef(den + sq, dm));
        float wgt = sig * omci * ath * rq;
        wa_lane += wgt * A;
        s_wb[k] = wgt * omi;
    }
    wa_lane = warp_sum(wa_lane);
    if (lane == 0) s_red[4 + warp] = wa_lane;
    __syncthreads();

    // ---- step 3: aggregation, unroll-2 dual accumulators (rows L1-hot) ----
    float4 uA = {0.f, 0.f, 0.f, 0.f};
    float4 uB = {0.f, 0.f, 0.f, 0.f};
    int k = warp;
    for (; k + 4 < cnt; k += 8) {
        float wbA = s_wb[k];
        float4 bA = *(const float4*)(x + s_idx[k] * DIM + 4 * lane);
        float wbB = s_wb[k + 4];
        float4 bB = *(const float4*)(x + s_idx[k + 4] * DIM + 4 * lane);
        uA.x += wbA * bA.x; uA.y += wbA * bA.y; uA.z += wbA * bA.z; uA.w += wbA * bA.w;
        uB.x += wbB * bB.x; uB.y += wbB * bB.y; uB.z += wbB * bB.z; uB.w += wbB * bB.w;
    }
    if (k < cnt) {
        float wbA = s_wb[k];
        float4 bA = *(const float4*)(x + s_idx[k] * DIM + 4 * lane);
        uA.x += wbA * bA.x; uA.y += wbA * bA.y; uA.z += wbA * bA.z; uA.w += wbA * bA.w;
    }
    uA.x += uB.x; uA.y += uB.y; uA.z += uB.z; uA.w += uB.w;
    ((float4*)s_u[warp])[lane] = uA;
    __syncthreads();

    // ---- step 4: expmap epilogue (warp 0, float4 per lane covers D=128) ----
    if (warp == 0) {
        float4 u0 = ((const float4*)s_u[0])[lane];
        float4 u1 = ((const float4*)s_u[1])[lane];
        float4 u2 = ((const float4*)s_u[2])[lane];
        float4 u3 = ((const float4*)s_u[3])[lane];
        float  wa = s_red[4] + s_red[5] + s_red[6] + s_red[7];
        float4 xi = ((const float4*)s_xi)[lane];
        float4 uu;
        uu.x = (u0.x + u1.x) + (u2.x + u3.x) - wa * xi.x;
        uu.y = (u0.y + u1.y) + (u2.y + u3.y) - wa * xi.y;
        uu.z = (u0.z + u1.z) + (u2.z + u3.z) - wa * xi.z;
        uu.w = (u0.w + u1.w) + (u2.w + u3.w) - wa * xi.w;
        float su2 = uu.x * uu.x + uu.y * uu.y + uu.z * uu.z + uu.w * uu.w;
        float sxu = xi.x * uu.x + xi.y * uu.y + xi.z * uu.z + xi.w * uu.w;
#pragma unroll
        for (int o = 16; o > 0; o >>= 1) {
            su2 += __shfl_xor_sync(FULLMASK, su2, o);
            sxu += __shfl_xor_sync(FULLMASK, sxu, o);
        }
        float un   = sqrtf(fmaxf(su2, 1e-15f));
        float coef = tanhf(un / omci) / un;     // tanh(lam*un/2)/un
        float xy   = coef * sxu;
        float y2   = coef * coef * su2;
        float den  = fmaxf(1.0f + 2.0f * xy + x2i * y2, 1e-15f);
        float An   = 1.0f + 2.0f * xy + y2;
        float Bn   = omi * coef;
        float inv  = 1.0f / den;
        float4 o;
        o.x = (An * xi.x + Bn * uu.x) * inv;
        o.y = (An * xi.y + Bn * uu.y) * inv;
        o.z = (An * xi.z + Bn * uu.z) * inv;
        o.w = (An * xi.w + Bn * uu.w) * inv;
        *(float4*)&out[i * DIM + 4 * lane] = o;
    }

    // ---- tail: last block resets flags (replay-safe) ----
    __syncthreads();                      // all reads of g_stat in block done
    if (t == 0) {
        __threadfence();
        int f = atomicAdd(&g_fin, 1);
        s_wcnt[0] = (f == (int)gridDim.x - 1);
    }
    __syncthreads();
    if (s_wcnt[0]) {                      // last block: zero the flag array
        for (int p = t; p < NPTS; p += 128) g_stat[p] = 0ull;
        if (t == 0) g_fin = 0;
    }
}

// ---------------------------------------------------------------------------
extern "C" void kernel_launch(void* const* d_in, const int* in_sizes, int n_in,
                              void* d_out, int out_size) {
    const float* x    = (const float*)d_in[0];   // [1,1024,128]
    const float* adj  = (const float*)d_in[1];   // [1,1024,1024]
    const float* attw = (const float*)d_in[2];   // [256]
    const float* attb = (const float*)d_in[3];   // scalar
    float* out = (float*)d_out;                  // [1,1024,128]

    k_fused<<<NPTS, 128>>>(x, adj, attw, attb, out);
}